// round 5
// baseline (speedup 1.0000x reference)
#include <cuda_runtime.h>
#include <math.h>

#define DD 64
#define KF 16
#define PP 2
#define NTASK (DD*PP)
#define NBLK 592            // SYRK blocks (4 per SM)
#define NPART (2*NBLK)      // one partial per (block, half)

__device__ __align__(16) float g_Gpart[NPART * DD * DD];
__device__ __align__(16) float g_G[DD * DD];
__device__ float g_task[NTASK];
__device__ int   g_ctr;     // zero-init; reset by last task block each run

// packed f32x2 helpers
__device__ __forceinline__ void fma2(unsigned long long& d,
                                     unsigned long long a,
                                     unsigned long long b) {
    asm("fma.rn.f32x2 %0, %1, %2, %0;" : "+l"(d) : "l"(a), "l"(b));
}
__device__ __forceinline__ unsigned long long pack2(float v) {
    unsigned long long r;
    asm("mov.b64 %0, {%1, %1};" : "=l"(r) : "f"(v));
    return r;
}

// ---------------------------------------------------------------------------
// Kernel 1: partial SYRK  Gpart = X_b^T X_b, upper-triangle 4x8 tiles,
// packed f32x2 FMA. 192 threads = 2 halves x 96 (72 active compute each).
// 4 blocks/SM for latency hiding.
// ---------------------------------------------------------------------------
__global__ __launch_bounds__(192) void k_syrk(const float* __restrict__ x,
                                              int n, int rows_per) {
    __shared__ __align__(32) float xs[32 * 64];   // 8 KB
    const int tid  = threadIdx.x;
    const int half = tid / 96;
    const int t2   = tid % 96;
    const bool active = (t2 < 72);

    int ti = 0, tj = 0;
    if (active) {
        int pr = t2;
        while (pr >= 8 - (ti >> 1)) { pr -= 8 - (ti >> 1); ti++; }
        tj = (ti >> 1) + pr;
    }

    unsigned long long acc[16];   // [ii][jp] : 4 rows x 4 f32x2 (8 cols)
#pragma unroll
    for (int i = 0; i < 16; i++) acc[i] = 0ull;

    const int row0 = blockIdx.x * rows_per;
    for (int t0 = 0; t0 < rows_per; t0 += 32) {
        // load 32x64 floats = 512 float4 with 192 threads
        for (int idx = tid; idx < 512; idx += 192) {
            int rr = idx >> 4, c4 = idx & 15;
            int lr = t0 + rr;
            int grow = row0 + lr;
            float4 v = make_float4(0.f, 0.f, 0.f, 0.f);
            if (lr < rows_per && grow < n)
                v = ((const float4*)x)[grow * 16 + c4];
            ((float4*)xs)[idx] = v;
        }
        __syncthreads();
        if (active) {
            const float* base = xs + half * (16 * 64);
#pragma unroll
            for (int rr = 0; rr < 16; rr++) {
                float4 a = *(const float4*)(base + rr * 64 + ti * 4);
                ulonglong2 b0 = *(const ulonglong2*)(base + rr * 64 + tj * 8);
                ulonglong2 b1 = *(const ulonglong2*)(base + rr * 64 + tj * 8 + 4);
                unsigned long long ax = pack2(a.x), ay = pack2(a.y);
                unsigned long long az = pack2(a.z), aw = pack2(a.w);
                fma2(acc[0],  ax, b0.x); fma2(acc[1],  ax, b0.y);
                fma2(acc[2],  ax, b1.x); fma2(acc[3],  ax, b1.y);
                fma2(acc[4],  ay, b0.x); fma2(acc[5],  ay, b0.y);
                fma2(acc[6],  ay, b1.x); fma2(acc[7],  ay, b1.y);
                fma2(acc[8],  az, b0.x); fma2(acc[9],  az, b0.y);
                fma2(acc[10], az, b1.x); fma2(acc[11], az, b1.y);
                fma2(acc[12], aw, b0.x); fma2(acc[13], aw, b0.y);
                fma2(acc[14], aw, b1.x); fma2(acc[15], aw, b1.y);
            }
        }
        __syncthreads();
    }

    if (active) {
        float* dst = g_Gpart + (size_t)(blockIdx.x * 2 + half) * (DD * DD)
                   + (ti * 4) * DD + tj * 8;
#pragma unroll
        for (int ii = 0; ii < 4; ii++) {
            unsigned long long a0 = acc[ii * 4 + 0], a1 = acc[ii * 4 + 1];
            unsigned long long a2 = acc[ii * 4 + 2], a3 = acc[ii * 4 + 3];
            float4 lo, hi;
            lo.x = __uint_as_float((unsigned)a0); lo.y = __uint_as_float((unsigned)(a0 >> 32));
            lo.z = __uint_as_float((unsigned)a1); lo.w = __uint_as_float((unsigned)(a1 >> 32));
            hi.x = __uint_as_float((unsigned)a2); hi.y = __uint_as_float((unsigned)(a2 >> 32));
            hi.z = __uint_as_float((unsigned)a3); hi.w = __uint_as_float((unsigned)(a3 >> 32));
            ((float4*)(dst + ii * DD))[0] = lo;
            ((float4*)(dst + ii * DD))[1] = hi;
        }
    }
}

// ---------------------------------------------------------------------------
// Kernel 2: reduce partials into full symmetric G. 256 blocks x 256 threads;
// block owns 16 entries, 16 threads per entry, 74 partials each (half-warp
// coalesced 64B reads, all L2-resident), smem tree across groups.
// ---------------------------------------------------------------------------
__global__ __launch_bounds__(256) void k_redG() {
    const int le = threadIdx.x & 15;           // entry lane
    const int g  = threadIdx.x >> 4;           // group 0..15
    const int e  = blockIdx.x * 16 + le;       // 0..4095
    const int i = e >> 6, j = e & 63;
    const int src = (i <= j) ? e : (j * 64 + i);

    const int per = NPART / 16;                // 74
    float s = 0.0f;
#pragma unroll 4
    for (int k = 0; k < per; k++)
        s += g_Gpart[(size_t)(g * per + k) * (DD * DD) + src];

    __shared__ float red[256];
    red[g * 16 + le] = s;
    __syncthreads();
    for (int ofs = 128; ofs >= 16; ofs >>= 1) {
        if (threadIdx.x < ofs) red[threadIdx.x] += red[threadIdx.x + ofs];
        __syncthreads();
    }
    if (threadIdx.x < 16) g_G[e] = red[threadIdx.x];
}

// ---------------------------------------------------------------------------
// Kernel 3: one block per (a,p) task, Woodbury through the K=16 factor space.
// Warp 0 inverts C (syncwarp only) WHILE warps 1-3 compute T and U.
// Final 128-task reduction folded in via atomic counter (deterministic tree).
// ---------------------------------------------------------------------------
__global__ __launch_bounds__(128) void k_tasks(const float* __restrict__ W,
                                               const int* __restrict__ perms,
                                               int n, float* __restrict__ out) {
    const int t   = blockIdx.x;
    const int m   = (t >> 1) + 1;     // P = 2
    const int r   = DD - m;
    const int tid = threadIdx.x;
    const int nt  = 128;

    __shared__ float Gsh[DD * DD];    // raw G; reused as T/U scratch later
    __shared__ float Gp[DD * DD];     // permuted G
    __shared__ float Wp[DD * KF];
    __shared__ float C[KF * KF];
    __shared__ float H[KF * KF];
    __shared__ float fcol[KF];
    __shared__ float tbuf[DD];
    __shared__ float fin[NTASK];
    __shared__ int   pm[DD];
    __shared__ int   isLast;

    if (tid < DD) pm[tid] = perms[t * DD + tid];
    for (int idx = tid; idx < 1024; idx += nt)
        ((float4*)Gsh)[idx] = ((const float4*)g_G)[idx];
    __syncthreads();

    for (int idx = tid; idx < DD * KF; idx += nt) {
        int i = idx >> 4, k = idx & 15;
        Wp[idx] = W[pm[i] * KF + k];
    }
    for (int idx = tid; idx < DD * DD; idx += nt) {
        int i = idx >> 6, j = idx & 63;
        Gp[idx] = Gsh[pm[i] * DD + pm[j]];
    }
    __syncthreads();

    // C = Wr^T Wr + 0.1 I  (all 128 threads, 2 entries each)
    for (int idx = tid; idx < KF * KF; idx += nt) {
        int s = idx >> 4, u = idx & 15;
        float acc = (s == u) ? 0.1f : 0.0f;
        for (int i = 0; i < r; i++)
            acc += Wp[(m + i) * KF + s] * Wp[(m + i) * KF + u];
        C[idx] = acc;
    }
    __syncthreads();

    // Gsh dead — alias scratch
    float* T = Gsh;                 // r x 16
    float* U = Gsh + 1024;          // m x 16

    if (tid < 32) {
        // warp 0: in-place Gauss-Jordan inverse of C (SPD), syncwarp only
        const int lane = tid;
        for (int k = 0; k < KF; k++) {
            if (lane < KF) fcol[lane] = C[lane * KF + k];
            __syncwarp();
            float ip = 1.0f / fcol[k];
            if (lane < KF)
                C[k * KF + lane] = (lane == k) ? ip : C[k * KF + lane] * ip;
            __syncwarp();
#pragma unroll
            for (int q = 0; q < 8; q++) {
                int idx = lane + 32 * q;
                int i = idx >> 4, j = idx & 15;
                if (i != k) {
                    float f = fcol[i];
                    C[idx] = (j == k) ? (-f * ip) : (C[idx] - f * C[k * KF + j]);
                }
            }
            __syncwarp();
        }
    } else {
        // warps 1-3: T = Gp_rr * Wr  and  U[j][s] = sum_i Wr[i][s]*Gp[m+i][j]
        const int t2 = tid - 32;
        for (int idx = t2; idx < r * KF; idx += 96) {
            int i = idx >> 4, s = idx & 15;
            float acc = 0.0f;
            for (int l = 0; l < r; l++)
                acc += Gp[(m + i) * DD + m + l] * Wp[(m + l) * KF + s];
            T[idx] = acc;
        }
        for (int idx = t2; idx < m * KF; idx += 96) {
            int j = idx >> 4, s = idx & 15;
            float acc = 0.0f;
            for (int i = 0; i < r; i++)
                acc += Wp[(m + i) * KF + s] * Gp[(m + i) * DD + j];
            U[idx] = acc;
        }
    }
    __syncthreads();

    // H = Wr^T * T   (16 x 16, all threads)
    for (int idx = tid; idx < KF * KF; idx += nt) {
        int s = idx >> 4, u = idx & 15;
        float acc = 0.0f;
        for (int i = 0; i < r; i++)
            acc += Wp[(m + i) * KF + s] * T[i * KF + u];
        H[idx] = acc;
    }
    __syncthreads();

    // per-column terms
    if (tid < m) {
        int j = tid;
        float w[KF], b[KF];
#pragma unroll
        for (int s = 0; s < KF; s++) w[s] = Wp[j * KF + s];
#pragma unroll
        for (int s = 0; s < KF; s++) {
            float acc = 0.0f;
#pragma unroll
            for (int u2 = 0; u2 < KF; u2++) acc += C[s * KF + u2] * w[u2];
            b[s] = acc;
        }
        float wb = 0.0f;
#pragma unroll
        for (int s = 0; s < KF; s++) wb += w[s] * b[s];
        float v = 0.1f * (1.0f + wb);

        float bu = 0.0f;
#pragma unroll
        for (int s = 0; s < KF; s++) bu += b[s] * U[j * KF + s];

        float bHb = 0.0f;
#pragma unroll
        for (int s = 0; s < KF; s++) {
            float acc = 0.0f;
#pragma unroll
            for (int u2 = 0; u2 < KF; u2++) acc += H[s * KF + u2] * b[u2];
            bHb += b[s] * acc;
        }
        float q = Gp[j * DD + j] - 2.0f * bu + bHb;

        const float LOG2PI = 1.8378770664093453f;
        tbuf[j] = -0.5f * logf(v) - 0.5f * LOG2PI - 0.5f * q / (v * (float)n);
    }
    __syncthreads();

    if (tid == 0) {
        float s = 0.0f;
        for (int j = 0; j < m; j++) s += tbuf[j];
        g_task[t] = s / (float)(PP * m);
    }

    // fold final reduction into the last-finishing block
    __threadfence();
    if (tid == 0) {
        int d = atomicAdd(&g_ctr, 1);
        isLast = (d == NTASK - 1);
    }
    __syncthreads();
    if (isLast) {
        fin[tid] = __ldcg(&g_task[tid]);   // nt == NTASK == 128
        __syncthreads();
        for (int ofs = NTASK / 2; ofs > 0; ofs >>= 1) {
            if (tid < ofs) fin[tid] += fin[tid + ofs];
            __syncthreads();
        }
        if (tid == 0) {
            out[0] = -fin[0];
            g_ctr = 0;                     // reset for next replay
        }
    }
}

// ---------------------------------------------------------------------------
extern "C" void kernel_launch(void* const* d_in, const int* in_sizes, int n_in,
                              void* d_out, int out_size) {
    const float* x = nullptr;
    const float* W = nullptr;
    const int* perms = nullptr;
    int nx = 0;
    for (int i = 0; i < n_in; i++) {
        if (in_sizes[i] == DD * KF)            W = (const float*)d_in[i];
        else if (in_sizes[i] == DD * PP * DD)  perms = (const int*)d_in[i];
        else { x = (const float*)d_in[i]; nx = in_sizes[i]; }
    }
    int n = nx / DD;
    int rows_per = ((n + NBLK - 1) / NBLK + 15) & ~15;   // 112 for n=65536

    k_syrk <<<NBLK, 192>>>(x, n, rows_per);
    k_redG <<<256, 256>>>();
    k_tasks<<<NTASK, 128>>>(W, perms, n, (float*)d_out);
}

// round 8
// speedup vs baseline: 1.1108x; 1.1108x over previous
#include <cuda_runtime.h>
#include <math.h>

#define DD 64
#define KF 16
#define PP 2
#define NTASK (DD*PP)
#define NBLK 592            // exactly one wave: 4 blocks/SM x 148 SMs
#define NPART NBLK          // halves combined in-block

__device__ __align__(16) float g_Gpart[NPART * DD * DD];
__device__ __align__(16) float g_G[DD * DD];
__device__ float g_task[NTASK];
__device__ int   g_ctr;          // task-done counter (reset each run)
__device__ int   g_bar[2];       // grid-barrier arrive counters
__device__ int   g_go[2];        // grid-barrier release flags
__device__ int   g_ack[2];       // grid-barrier ack counters (for reset)

// packed f32x2 helpers
__device__ __forceinline__ void fma2(unsigned long long& d,
                                     unsigned long long a,
                                     unsigned long long b) {
    asm("fma.rn.f32x2 %0, %1, %2, %0;" : "+l"(d) : "l"(a), "l"(b));
}
__device__ __forceinline__ unsigned long long pack2(float v) {
    unsigned long long r;
    asm("mov.b64 %0, {%1, %1};" : "=l"(r) : "f"(v));
    return r;
}
__device__ __forceinline__ float lo32(unsigned long long v) {
    return __uint_as_float((unsigned)v);
}
__device__ __forceinline__ float hi32(unsigned long long v) {
    return __uint_as_float((unsigned)(v >> 32));
}

// Replay-safe grid barrier. All gridDim.x blocks are co-resident (one wave:
// 592 blocks at 4/SM guaranteed by __launch_bounds__(192,4) + 40KB smem).
// arrive -> last resets arrive ctr + sets go; others spin; ack's last
// resets go + ack. All state returns to 0 for the next graph replay.
__device__ __forceinline__ void grid_barrier(int id) {
    __syncthreads();
    if (threadIdx.x == 0) {
        const int nb = (int)gridDim.x;
        __threadfence();
        int v = atomicAdd(&g_bar[id], 1);
        if (v == nb - 1) {
            g_bar[id] = 0;
            __threadfence();
            atomicExch(&g_go[id], 1);
        } else {
            while (atomicAdd(&g_go[id], 0) == 0) { __nanosleep(64); }
        }
        int a = atomicAdd(&g_ack[id], 1);
        if (a == nb - 1) {
            g_ack[id] = 0;
            atomicExch(&g_go[id], 0);
        }
    }
    __syncthreads();
}

struct SmemC {
    float Gsh[DD * DD];
    float Gp[DD * DD];
    float Wp[DD * KF];
    float C[KF * KF];
    float H[KF * KF];
    float fcol[KF];
    float tbuf[DD];
    float fin[NTASK];
    int   pm[DD];
    int   isLast;
};
union Smem {
    struct {
        float xs[32 * 64];                    // 8 KB tile
        unsigned long long comb[72 * 16];     // 9 KB half-combine
    } a;
    float red[192];                           // phase B
    SmemC c;                                  // phase C (~39.1 KB)
};

// ---------------------------------------------------------------------------
__global__ __launch_bounds__(192, 4)
void k_fused(const float* __restrict__ x, int n, int rows_per,
             const float* __restrict__ W, const int* __restrict__ perms,
             float* __restrict__ out) {
    __shared__ Smem sm;
    const int tid = threadIdx.x;
    const int bid = blockIdx.x;

    // ================= Phase A: partial SYRK =================
    {
        const int half = tid / 96;
        const int t2   = tid % 96;
        const bool active = (t2 < 72);

        int ti = 0, tj = 0;
        if (active) {
            int pr = t2;
            while (pr >= 8 - (ti >> 1)) { pr -= 8 - (ti >> 1); ti++; }
            tj = (ti >> 1) + pr;
        }

        unsigned long long acc[16];
#pragma unroll
        for (int i = 0; i < 16; i++) acc[i] = 0ull;

        const int row0 = bid * rows_per;
        for (int t0 = 0; t0 < rows_per; t0 += 32) {
            for (int idx = tid; idx < 512; idx += 192) {
                int rr = idx >> 4, c4 = idx & 15;
                int grow = row0 + t0 + rr;
                float4 v = make_float4(0.f, 0.f, 0.f, 0.f);
                if (grow < n) v = ((const float4*)x)[grow * 16 + c4];
                ((float4*)sm.a.xs)[idx] = v;
            }
            __syncthreads();
            if (active) {
                const float* base = sm.a.xs + half * (16 * 64);
#pragma unroll
                for (int rr = 0; rr < 16; rr++) {
                    float4 a = *(const float4*)(base + rr * 64 + ti * 4);
                    ulonglong2 b0 = *(const ulonglong2*)(base + rr * 64 + tj * 8);
                    ulonglong2 b1 = *(const ulonglong2*)(base + rr * 64 + tj * 8 + 4);
                    unsigned long long ax = pack2(a.x), ay = pack2(a.y);
                    unsigned long long az = pack2(a.z), aw = pack2(a.w);
                    fma2(acc[0],  ax, b0.x); fma2(acc[1],  ax, b0.y);
                    fma2(acc[2],  ax, b1.x); fma2(acc[3],  ax, b1.y);
                    fma2(acc[4],  ay, b0.x); fma2(acc[5],  ay, b0.y);
                    fma2(acc[6],  ay, b1.x); fma2(acc[7],  ay, b1.y);
                    fma2(acc[8],  az, b0.x); fma2(acc[9],  az, b0.y);
                    fma2(acc[10], az, b1.x); fma2(acc[11], az, b1.y);
                    fma2(acc[12], aw, b0.x); fma2(acc[13], aw, b0.y);
                    fma2(acc[14], aw, b1.x); fma2(acc[15], aw, b1.y);
                }
            }
            __syncthreads();
        }

        // combine halves inside the block -> single partial per block
        if (half == 1 && active) {
#pragma unroll
            for (int k = 0; k < 16; k++) sm.a.comb[t2 * 16 + k] = acc[k];
        }
        __syncthreads();
        if (half == 0 && active) {
            float* dst = g_Gpart + (size_t)bid * (DD * DD) + (ti * 4) * DD + tj * 8;
#pragma unroll
            for (int ii = 0; ii < 4; ii++) {
                float4 lov, hiv;
                unsigned long long m0 = acc[ii * 4 + 0], o0 = sm.a.comb[t2 * 16 + ii * 4 + 0];
                unsigned long long m1 = acc[ii * 4 + 1], o1 = sm.a.comb[t2 * 16 + ii * 4 + 1];
                unsigned long long m2 = acc[ii * 4 + 2], o2 = sm.a.comb[t2 * 16 + ii * 4 + 2];
                unsigned long long m3 = acc[ii * 4 + 3], o3 = sm.a.comb[t2 * 16 + ii * 4 + 3];
                lov.x = lo32(m0) + lo32(o0); lov.y = hi32(m0) + hi32(o0);
                lov.z = lo32(m1) + lo32(o1); lov.w = hi32(m1) + hi32(o1);
                hiv.x = lo32(m2) + lo32(o2); hiv.y = hi32(m2) + hi32(o2);
                hiv.z = lo32(m3) + lo32(o3); hiv.w = hi32(m3) + hi32(o3);
                ((float4*)(dst + ii * DD))[0] = lov;
                ((float4*)(dst + ii * DD))[1] = hiv;
            }
        }
    }

    grid_barrier(0);

    // ================= Phase B: reduce partials into G =================
    if (bid < 256) {
        const int le = tid & 15;               // entry lane (coalesced)
        const int g  = tid >> 4;               // group 0..11
        const int e  = bid * 16 + le;          // 0..4095
        const int i = e >> 6, j = e & 63;
        const int src = (i <= j) ? e : (j * 64 + i);

        float s = 0.0f;
#pragma unroll 5
        for (int p = g; p < NPART; p += 12)
            s += g_Gpart[(size_t)p * (DD * DD) + src];

        sm.red[tid] = s;
        __syncthreads();
        if (tid < 64) sm.red[tid] += sm.red[tid + 128];
        __syncthreads();
        if (tid < 64) sm.red[tid] += sm.red[tid + 64];
        __syncthreads();
        if (tid < 32) sm.red[tid] += sm.red[tid + 32];
        __syncthreads();
        if (tid < 16) {
            g_G[e] = sm.red[tid] + sm.red[tid + 16];
        }
    }

    grid_barrier(1);

    // ================= Phase C: 128 task blocks =================
    if (bid >= NTASK) return;
    {
        const int t  = bid;
        const int m  = (t >> 1) + 1;      // P = 2
        const int r  = DD - m;
        const int nt = 192;
        SmemC& S = sm.c;

        if (tid < DD) S.pm[tid] = perms[t * DD + tid];
        for (int idx = tid; idx < 1024; idx += nt)
            ((float4*)S.Gsh)[idx] = ((const float4*)g_G)[idx];
        __syncthreads();

        for (int idx = tid; idx < DD * KF; idx += nt) {
            int i = idx >> 4, k = idx & 15;
            S.Wp[idx] = W[S.pm[i] * KF + k];
        }
        for (int idx = tid; idx < DD * DD; idx += nt) {
            int i = idx >> 6, j = idx & 63;
            S.Gp[idx] = S.Gsh[S.pm[i] * DD + S.pm[j]];
        }
        __syncthreads();

        // C = Wr^T Wr + 0.1 I
        for (int idx = tid; idx < KF * KF; idx += nt) {
            int s = idx >> 4, u = idx & 15;
            float acc = (s == u) ? 0.1f : 0.0f;
            for (int i = 0; i < r; i++)
                acc += S.Wp[(m + i) * KF + s] * S.Wp[(m + i) * KF + u];
            S.C[idx] = acc;
        }
        __syncthreads();

        float* T = S.Gsh;            // r x 16 (Gsh dead)
        float* U = S.Gsh + 1024;     // m x 16

        if (tid < 32) {
            // warp 0: Gauss-Jordan inverse of C (SPD), syncwarp only
            const int lane = tid;
            for (int k = 0; k < KF; k++) {
                if (lane < KF) S.fcol[lane] = S.C[lane * KF + k];
                __syncwarp();
                float ip = 1.0f / S.fcol[k];
                if (lane < KF)
                    S.C[k * KF + lane] = (lane == k) ? ip : S.C[k * KF + lane] * ip;
                __syncwarp();
#pragma unroll
                for (int q = 0; q < 8; q++) {
                    int idx = lane + 32 * q;
                    int i = idx >> 4, j = idx & 15;
                    if (i != k) {
                        float f = S.fcol[i];
                        S.C[idx] = (j == k) ? (-f * ip) : (S.C[idx] - f * S.C[k * KF + j]);
                    }
                }
                __syncwarp();
            }
        } else {
            // warps 1-5: T = Gp_rr * Wr  and  U[j][s] = sum_i Wr[i][s]*Gp[m+i][j]
            const int t2 = tid - 32;
            for (int idx = t2; idx < r * KF; idx += 160) {
                int i = idx >> 4, s = idx & 15;
                float acc = 0.0f;
                for (int l = 0; l < r; l++)
                    acc += S.Gp[(m + i) * DD + m + l] * S.Wp[(m + l) * KF + s];
                T[idx] = acc;
            }
            for (int idx = t2; idx < m * KF; idx += 160) {
                int j = idx >> 4, s = idx & 15;
                float acc = 0.0f;
                for (int i = 0; i < r; i++)
                    acc += S.Wp[(m + i) * KF + s] * S.Gp[(m + i) * DD + j];
                U[idx] = acc;
            }
        }
        __syncthreads();

        // H = Wr^T * T
        for (int idx = tid; idx < KF * KF; idx += nt) {
            int s = idx >> 4, u = idx & 15;
            float acc = 0.0f;
            for (int i = 0; i < r; i++)
                acc += S.Wp[(m + i) * KF + s] * T[i * KF + u];
            S.H[idx] = acc;
        }
        __syncthreads();

        if (tid < m) {
            int j = tid;
            float w[KF], b[KF];
#pragma unroll
            for (int s = 0; s < KF; s++) w[s] = S.Wp[j * KF + s];
#pragma unroll
            for (int s = 0; s < KF; s++) {
                float acc = 0.0f;
#pragma unroll
                for (int u2 = 0; u2 < KF; u2++) acc += S.C[s * KF + u2] * w[u2];
                b[s] = acc;
            }
            float wb = 0.0f;
#pragma unroll
            for (int s = 0; s < KF; s++) wb += w[s] * b[s];
            float v = 0.1f * (1.0f + wb);

            float bu = 0.0f;
#pragma unroll
            for (int s = 0; s < KF; s++) bu += b[s] * U[j * KF + s];

            float bHb = 0.0f;
#pragma unroll
            for (int s = 0; s < KF; s++) {
                float acc = 0.0f;
#pragma unroll
                for (int u2 = 0; u2 < KF; u2++) acc += S.H[s * KF + u2] * b[u2];
                bHb += b[s] * acc;
            }
            float q = S.Gp[j * DD + j] - 2.0f * bu + bHb;

            const float LOG2PI = 1.8378770664093453f;
            S.tbuf[j] = -0.5f * logf(v) - 0.5f * LOG2PI - 0.5f * q / (v * (float)n);
        }
        __syncthreads();

        if (tid == 0) {
            float s = 0.0f;
            for (int j = 0; j < m; j++) s += S.tbuf[j];
            g_task[t] = s / (float)(PP * m);
        }

        // last-finishing task block does the final 128-value reduction
        __threadfence();
        if (tid == 0) {
            int d = atomicAdd(&g_ctr, 1);
            S.isLast = (d == NTASK - 1);
        }
        __syncthreads();
        if (S.isLast) {
            if (tid < NTASK) S.fin[tid] = __ldcg(&g_task[tid]);
            __syncthreads();
            for (int ofs = NTASK / 2; ofs > 0; ofs >>= 1) {
                if (tid < ofs) S.fin[tid] += S.fin[tid + ofs];
                __syncthreads();
            }
            if (tid == 0) {
                out[0] = -S.fin[0];
                g_ctr = 0;
            }
        }
    }
}

// ---------------------------------------------------------------------------
extern "C" void kernel_launch(void* const* d_in, const int* in_sizes, int n_in,
                              void* d_out, int out_size) {
    const float* x = nullptr;
    const float* W = nullptr;
    const int* perms = nullptr;
    int nx = 0;
    for (int i = 0; i < n_in; i++) {
        if (in_sizes[i] == DD * KF)            W = (const float*)d_in[i];
        else if (in_sizes[i] == DD * PP * DD)  perms = (const int*)d_in[i];
        else { x = (const float*)d_in[i]; nx = in_sizes[i]; }
    }
    int n = nx / DD;
    int rows_per = ((n + NBLK - 1) / NBLK + 31) & ~31;   // 128 for n=65536

    k_fused<<<NBLK, 192>>>(x, n, rows_per, W, perms, (float*)d_out);
}

// round 9
// speedup vs baseline: 1.3124x; 1.1814x over previous
#include <cuda_runtime.h>
#include <math.h>

#define DD 64
#define KF 16
#define PP 2
#define NTASK (DD*PP)
#define NBLK 512            // 512 x 128 rows = 65536 exactly; one wave (4/SM cap)
#define NPART NBLK
#define NRED  256           // phase-B blocks (bid 256..511)

__device__ __align__(16) float g_Gpart[NPART * DD * DD];
__device__ __align__(16) float g_G[DD * DD];
__device__ float g_task[NTASK];
__device__ int   g_ctr;              // reset by last task block
__device__ int   g_bar[2];           // arrive counters (self-reset at release)
__device__ volatile int g_go[2];     // release flags (reset by last task block)

// packed f32x2 helpers
__device__ __forceinline__ void fma2(unsigned long long& d,
                                     unsigned long long a,
                                     unsigned long long b) {
    asm("fma.rn.f32x2 %0, %1, %2, %0;" : "+l"(d) : "l"(a), "l"(b));
}
__device__ __forceinline__ unsigned long long pack2(float v) {
    unsigned long long r;
    asm("mov.b64 %0, {%1, %1};" : "=l"(r) : "f"(v));
    return r;
}
__device__ __forceinline__ float lo32(unsigned long long v) {
    return __uint_as_float((unsigned)v);
}
__device__ __forceinline__ float hi32(unsigned long long v) {
    return __uint_as_float((unsigned)(v >> 32));
}

// arrive-only / wait-only grid barrier. Polling is a volatile LOAD (L2
// broadcast, no atomic-ALU serialization), arrive is one atomicAdd per block.
__device__ __forceinline__ void bar_arrive(int id, int total) {
    __syncthreads();
    if (threadIdx.x == 0) {
        __threadfence();
        int v = atomicAdd(&g_bar[id], 1);
        if (v == total - 1) {
            g_bar[id] = 0;       // self-reset for next replay
            __threadfence();
            g_go[id] = 1;
        }
    }
}
__device__ __forceinline__ void bar_wait(int id) {
    if (threadIdx.x == 0) {
        while (g_go[id] == 0) { __nanosleep(64); }
    }
    __syncthreads();
    __threadfence();
}

struct SmemC {
    float Gsh[DD * DD];      // 16 KB
    float Wm[DD * KF];       // masked W
    float wjs[DD * KF];      // w_j gathers (rows j < m)
    float Tfull[DD * KF];    // G @ Wm
    float C[KF * KF];        // -> C^-1 in place
    float H[KF * KF];
    float fcol[KF];
    float Mf[DD];
    float tbuf[DD];
    float fin[NTASK];
    int   pm[DD];
    int   isLast;
};
union Smem {
    struct {
        float xs[2 * 32 * 64];                // 16 KB double buffer
        unsigned long long comb[72 * 16];     // 9 KB half-combine
    } a;
    float red[192];
    SmemC c;                                  // ~31.5 KB
};

// ---------------------------------------------------------------------------
__global__ __launch_bounds__(192, 4)
void k_fused(const float* __restrict__ x, int n, int rows_per,
             const float* __restrict__ W, const int* __restrict__ perms,
             float* __restrict__ out) {
    __shared__ Smem sm;
    const int tid = threadIdx.x;
    const int bid = blockIdx.x;

    // ================= Phase A: partial SYRK (cp.async double-buffered) ====
    {
        const int half = tid / 96;
        const int t2   = tid % 96;
        const bool active = (t2 < 72);

        int ti = 0, tj = 0;
        if (active) {
            int pr = t2;
            while (pr >= 8 - (ti >> 1)) { pr -= 8 - (ti >> 1); ti++; }
            tj = (ti >> 1) + pr;
        }

        unsigned long long acc[16];
#pragma unroll
        for (int i = 0; i < 16; i++) acc[i] = 0ull;

        const int row0 = bid * rows_per;
        const int nT = rows_per / 32;
        const unsigned sb = (unsigned)__cvta_generic_to_shared(sm.a.xs);

        // issue tile t into buffer buf
        auto load_tile = [&](int t, int buf) {
            int base = row0 + t * 32;
            for (int idx = tid; idx < 512; idx += 192) {
                int rr = idx >> 4, c4 = idx & 15;
                int grow = base + rr;
                const float4* src = ((const float4*)x) + (size_t)grow * 16 + c4;
                unsigned dst = sb + (unsigned)(buf * 8192 + idx * 16);
                int sz = (grow < n) ? 16 : 0;
                asm volatile("cp.async.cg.shared.global [%0], [%1], 16, %2;"
                             :: "r"(dst), "l"(src), "r"(sz));
            }
            asm volatile("cp.async.commit_group;");
        };

        load_tile(0, 0);
        for (int t = 0; t < nT; t++) {
            if (t + 1 < nT) {
                load_tile(t + 1, (t + 1) & 1);
                asm volatile("cp.async.wait_group 1;");
            } else {
                asm volatile("cp.async.wait_group 0;");
            }
            __syncthreads();
            if (active) {
                const float* base = sm.a.xs + (t & 1) * 2048 + half * 1024;
#pragma unroll
                for (int rr = 0; rr < 16; rr++) {
                    float4 a = *(const float4*)(base + rr * 64 + ti * 4);
                    ulonglong2 b0 = *(const ulonglong2*)(base + rr * 64 + tj * 8);
                    ulonglong2 b1 = *(const ulonglong2*)(base + rr * 64 + tj * 8 + 4);
                    unsigned long long ax = pack2(a.x), ay = pack2(a.y);
                    unsigned long long az = pack2(a.z), aw = pack2(a.w);
                    fma2(acc[0],  ax, b0.x); fma2(acc[1],  ax, b0.y);
                    fma2(acc[2],  ax, b1.x); fma2(acc[3],  ax, b1.y);
                    fma2(acc[4],  ay, b0.x); fma2(acc[5],  ay, b0.y);
                    fma2(acc[6],  ay, b1.x); fma2(acc[7],  ay, b1.y);
                    fma2(acc[8],  az, b0.x); fma2(acc[9],  az, b0.y);
                    fma2(acc[10], az, b1.x); fma2(acc[11], az, b1.y);
                    fma2(acc[12], aw, b0.x); fma2(acc[13], aw, b0.y);
                    fma2(acc[14], aw, b1.x); fma2(acc[15], aw, b1.y);
                }
            }
            __syncthreads();
        }

        // combine halves in-block -> one partial per block
        if (half == 1 && active) {
#pragma unroll
            for (int k = 0; k < 16; k++) sm.a.comb[t2 * 16 + k] = acc[k];
        }
        __syncthreads();
        if (half == 0 && active) {
            float* dst = g_Gpart + (size_t)bid * (DD * DD) + (ti * 4) * DD + tj * 8;
#pragma unroll
            for (int ii = 0; ii < 4; ii++) {
                float4 lov, hiv;
                unsigned long long m0 = acc[ii*4+0], o0 = sm.a.comb[t2*16 + ii*4+0];
                unsigned long long m1 = acc[ii*4+1], o1 = sm.a.comb[t2*16 + ii*4+1];
                unsigned long long m2 = acc[ii*4+2], o2 = sm.a.comb[t2*16 + ii*4+2];
                unsigned long long m3 = acc[ii*4+3], o3 = sm.a.comb[t2*16 + ii*4+3];
                lov.x = lo32(m0)+lo32(o0); lov.y = hi32(m0)+hi32(o0);
                lov.z = lo32(m1)+lo32(o1); lov.w = hi32(m1)+hi32(o1);
                hiv.x = lo32(m2)+lo32(o2); hiv.y = hi32(m2)+hi32(o2);
                hiv.z = lo32(m3)+lo32(o3); hiv.w = hi32(m3)+hi32(o3);
                ((float4*)(dst + ii * DD))[0] = lov;
                ((float4*)(dst + ii * DD))[1] = hiv;
            }
        }
    }

    bar_arrive(0, NBLK);

    // ================= Blocks 256..511: phase B then exit ==================
    if (bid >= 256) {
        bar_wait(0);
        const int le = tid & 15;
        const int g  = tid >> 4;                  // 0..11
        const int e  = (bid - 256) * 16 + le;     // 0..4095
        const int i = e >> 6, j = e & 63;
        const int src = (i <= j) ? e : (j * 64 + i);

        float s = 0.0f;
        for (int p = g; p < NPART; p += 12)
            s += g_Gpart[(size_t)p * (DD * DD) + src];

        sm.red[tid] = s;
        __syncthreads();
        if (tid < 64) sm.red[tid] += sm.red[tid + 128];
        __syncthreads();
        if (tid < 64) sm.red[tid] += sm.red[tid + 64];
        __syncthreads();
        if (tid < 32) sm.red[tid] += sm.red[tid + 32];
        __syncthreads();
        if (tid < 16) g_G[e] = sm.red[tid] + sm.red[tid + 16];

        bar_arrive(1, NRED);
        return;
    }
    if (bid >= NTASK) return;    // blocks 128..255: arrived bar0, done

    // ================= Blocks 0..127: task math ============================
    {
        const int t  = bid;
        const int m  = (t >> 1) + 1;      // P = 2
        const int nt = 192;
        SmemC& S = sm.c;

        // ---- W-only pre-phase (overlaps phase B) ----
        if (tid < DD) { S.pm[tid] = perms[t * DD + tid]; S.Mf[tid] = 0.0f; }
        __syncthreads();
        if (tid >= m && tid < DD) S.Mf[S.pm[tid]] = 1.0f;   // rest-set mask
        __syncthreads();

        for (int idx = tid; idx < DD * KF; idx += nt) {
            int o = idx >> 4;
            S.Wm[idx] = W[idx] * S.Mf[o];                   // coalesced
        }
        for (int idx = tid; idx < m * KF; idx += nt) {
            int j = idx >> 4, s = idx & 15;
            S.wjs[idx] = W[S.pm[j] * KF + s];
        }
        __syncthreads();

        // C = Wm^T Wm + 0.1 I   (== Wr^T Wr + 0.1 I)
        for (int idx = tid; idx < KF * KF; idx += nt) {
            int s = idx >> 4, u = idx & 15;
            float acc = (s == u) ? 0.1f : 0.0f;
            for (int o = 0; o < DD; o++)
                acc += S.Wm[o * KF + s] * S.Wm[o * KF + u];
            S.C[idx] = acc;
        }
        __syncthreads();

        // warp 0: Gauss-Jordan inverse of C (SPD), syncwarp only
        if (tid < 32) {
            const int lane = tid;
            for (int k = 0; k < KF; k++) {
                if (lane < KF) S.fcol[lane] = S.C[lane * KF + k];
                __syncwarp();
                float ip = 1.0f / S.fcol[k];
                if (lane < KF)
                    S.C[k * KF + lane] = (lane == k) ? ip : S.C[k * KF + lane] * ip;
                __syncwarp();
#pragma unroll
                for (int q = 0; q < 8; q++) {
                    int idx = lane + 32 * q;
                    int i = idx >> 4, j = idx & 15;
                    if (i != k) {
                        float f = S.fcol[i];
                        S.C[idx] = (j == k) ? (-f * ip) : (S.C[idx] - f * S.C[k * KF + j]);
                    }
                }
                __syncwarp();
            }
        }
        __syncthreads();

        // ---- G-dependent post-phase ----
        bar_wait(1);

        for (int idx = tid; idx < 1024; idx += nt)
            ((float4*)S.Gsh)[idx] = ((const float4*)g_G)[idx];
        __syncthreads();

        // Tfull = G @ Wm  (64 x 16, coalesced, no permutation)
        for (int idx = tid; idx < DD * KF; idx += nt) {
            int d = idx >> 4, s = idx & 15;
            float acc = 0.0f;
            for (int o = 0; o < DD; o++)
                acc += S.Gsh[d * DD + o] * S.Wm[o * KF + s];
            S.Tfull[idx] = acc;
        }
        __syncthreads();

        // H = Wm^T @ Tfull  (16 x 16)
        for (int idx = tid; idx < KF * KF; idx += nt) {
            int s = idx >> 4, u = idx & 15;
            float acc = 0.0f;
            for (int o = 0; o < DD; o++)
                acc += S.Wm[o * KF + s] * S.Tfull[o * KF + u];
            S.H[idx] = acc;
        }
        __syncthreads();

        // per-column terms: b = C^-1 w;  v = 0.1(1 + w.b)
        // q = G[pmj][pmj] - 2 b.Tfull[pmj] + b^T H b
        if (tid < m) {
            int j = tid;
            int pj = S.pm[j];
            float w[KF], b[KF];
#pragma unroll
            for (int s = 0; s < KF; s++) w[s] = S.wjs[j * KF + s];
#pragma unroll
            for (int s = 0; s < KF; s++) {
                float acc = 0.0f;
#pragma unroll
                for (int u2 = 0; u2 < KF; u2++) acc += S.C[s * KF + u2] * w[u2];
                b[s] = acc;
            }
            float wb = 0.0f, bu = 0.0f;
#pragma unroll
            for (int s = 0; s < KF; s++) {
                wb += w[s] * b[s];
                bu += b[s] * S.Tfull[pj * KF + s];
            }
            float v = 0.1f * (1.0f + wb);

            float bHb = 0.0f;
#pragma unroll
            for (int s = 0; s < KF; s++) {
                float acc = 0.0f;
#pragma unroll
                for (int u2 = 0; u2 < KF; u2++) acc += S.H[s * KF + u2] * b[u2];
                bHb += b[s] * acc;
            }
            float q = S.Gsh[pj * DD + pj] - 2.0f * bu + bHb;

            const float LOG2PI = 1.8378770664093453f;
            S.tbuf[j] = -0.5f * logf(v) - 0.5f * LOG2PI - 0.5f * q / (v * (float)n);
        }
        __syncthreads();

        if (tid == 0) {
            float s = 0.0f;
            for (int j = 0; j < m; j++) s += S.tbuf[j];
            g_task[t] = s / (float)(PP * m);
        }

        // last-finishing task block: final reduce + state reset
        __threadfence();
        if (tid == 0) {
            int d = atomicAdd(&g_ctr, 1);
            S.isLast = (d == NTASK - 1);
        }
        __syncthreads();
        if (S.isLast) {
            if (tid < NTASK) S.fin[tid] = __ldcg(&g_task[tid]);
            __syncthreads();
            for (int ofs = NTASK / 2; ofs > 0; ofs >>= 1) {
                if (tid < ofs && tid + ofs < NTASK) S.fin[tid] += S.fin[tid + ofs];
                __syncthreads();
            }
            if (tid == 0) {
                out[0] = -S.fin[0];
                g_ctr = 0;
                g_go[0] = 0;
                g_go[1] = 0;
            }
        }
    }
}

// ---------------------------------------------------------------------------
extern "C" void kernel_launch(void* const* d_in, const int* in_sizes, int n_in,
                              void* d_out, int out_size) {
    const float* x = nullptr;
    const float* W = nullptr;
    const int* perms = nullptr;
    int nx = 0;
    for (int i = 0; i < n_in; i++) {
        if (in_sizes[i] == DD * KF)            W = (const float*)d_in[i];
        else if (in_sizes[i] == DD * PP * DD)  perms = (const int*)d_in[i];
        else { x = (const float*)d_in[i]; nx = in_sizes[i]; }
    }
    int n = nx / DD;
    int rows_per = ((n + NBLK - 1) / NBLK + 31) & ~31;   // 128 exact for n=65536

    k_fused<<<NBLK, 192>>>(x, n, rows_per, W, perms, (float*)d_out);
}

// round 15
// speedup vs baseline: 1.6429x; 1.2518x over previous
#include <cuda_runtime.h>
#include <cuda_bf16.h>
#include <stdint.h>
#include <math.h>

#define DD 64
#define KF 16
#define PP 2
#define NTASK 128
#define NBLK 256
#define NPART 256

__device__ __align__(16) float g_Gpart[NPART * DD * DD];
__device__ __align__(16) float g_G[DD * DD];
__device__ float g_task[NTASK];
__device__ int   g_ctr;
__device__ int   g_bar[2];
__device__ volatile int g_go[2];

// ---------------- warp-MMA helpers (baseline PTX, sm_80+) ----------------
__device__ __forceinline__ uint32_t smem_u32(const void* p) {
    uint32_t a;
    asm("{ .reg .u64 t; cvta.to.shared.u64 t, %1; cvt.u32.u64 %0, t; }"
        : "=r"(a) : "l"(p));
    return a;
}
__device__ __forceinline__ void ldsm4(uint32_t* r, uint32_t addr) {
    asm volatile("ldmatrix.sync.aligned.m8n8.x4.shared.b16 {%0,%1,%2,%3}, [%4];"
                 : "=r"(r[0]), "=r"(r[1]), "=r"(r[2]), "=r"(r[3]) : "r"(addr));
}
__device__ __forceinline__ void mma16816(float* c, const uint32_t* a,
                                         const uint32_t* b) {
    asm volatile(
        "mma.sync.aligned.m16n8k16.row.col.f32.bf16.bf16.f32 "
        "{%0,%1,%2,%3}, {%4,%5,%6,%7}, {%8,%9}, {%0,%1,%2,%3};"
        : "+f"(c[0]), "+f"(c[1]), "+f"(c[2]), "+f"(c[3])
        : "r"(a[0]), "r"(a[1]), "r"(a[2]), "r"(a[3]), "r"(b[0]), "r"(b[1]));
}
// swizzled smem byte address: 128B rows, SW128 (off ^ ((off>>3)&0x70))
__device__ __forceinline__ uint32_t swz(uint32_t base, int row, int kb) {
    uint32_t off = (uint32_t)row * 128u + (uint32_t)kb;
    return base + (off ^ ((off >> 3) & 0x70u));
}

// ---------------- shared layouts ----------------
struct SmemC {
    float Gsh[DD * DD];
    float Wm[DD * KF];
    float wjs[DD * KF];
    float Tfull[DD * KF];
    float C[KF * KF];
    float H[KF * KF];
    float fcol[KF];
    float Mf[DD];
    float tbuf[DD];
    float fin[NTASK];
    int   pm[DD];
    int   isLast;
};
struct SmemA {
    __align__(1024) __nv_bfloat16 zh[64 * 64];   // 8 KB, 128B rows
    __align__(1024) __nv_bfloat16 zl[64 * 64];   // 8 KB
};
union Smem {
    SmemA a;
    float comb[64 * 65];      // 16.6 KB (used after MMA; overlaps z)
    float red[128];
    SmemC c;
};

// grid barrier: arrive-only + volatile-load wait (replay-safe)
__device__ __forceinline__ void bar_arrive(int id, int total) {
    __syncthreads();
    if (threadIdx.x == 0) {
        __threadfence();
        int v = atomicAdd(&g_bar[id], 1);
        if (v == total - 1) {
            g_bar[id] = 0;
            __threadfence();
            g_go[id] = 1;
        }
    }
}
__device__ __forceinline__ void bar_wait(int id) {
    if (threadIdx.x == 0) {
        while (g_go[id] == 0) { __nanosleep(64); }
    }
    __syncthreads();
    __threadfence();
}

// ---------------------------------------------------------------------------
__global__ __launch_bounds__(128, 2)
void k_fused(const float* __restrict__ x, int n, int tpb,
             const float* __restrict__ W, const int* __restrict__ perms,
             float* __restrict__ out) {
    __shared__ Smem sm;
    const int tid = threadIdx.x;
    const int bid = blockIdx.x;
    const int wid = tid >> 5;
    const int lane = tid & 31;

    // ================= Phase A: split-bf16 SYRK on mma.sync ================
    {
        const int ntiles = tpb >> 6;
        const int feat = tid & 63;
        const bool isL = (tid >= 64);
        const uint32_t zhb = smem_u32(sm.a.zh);
        const uint32_t zlb = smem_u32(sm.a.zl);
        const int r0w = wid * 16;              // this warp's output rows

        float d00[32], d01[32], d11[32];
#pragma unroll
        for (int i = 0; i < 32; i++) { d00[i] = 0.f; d01[i] = 0.f; d11[i] = 0.f; }

        for (int t = 0; t < ntiles; t++) {
            // ---- stage h/l tiles: thread = (feature, half), 64 tokens ----
            const long tokg = (long)bid * tpb + (long)t * 64;
            const uint32_t zb = isL ? zlb : zhb;
#pragma unroll
            for (int g8 = 0; g8 < 8; g8++) {
                uint32_t wr0, wr1, wr2, wr3;
                {
                    uint32_t wr[4];
#pragma unroll
                    for (int k = 0; k < 4; k++) {
                        long t0 = tokg + g8 * 8 + 2 * k;
                        float v0 = (t0     < n) ? x[t0 * 64 + feat]       : 0.0f;
                        float v1 = (t0 + 1 < n) ? x[(t0 + 1) * 64 + feat] : 0.0f;
                        unsigned short b0, b1;
                        if (!isL) {
                            b0 = __bfloat16_as_ushort(__float2bfloat16(v0));
                            b1 = __bfloat16_as_ushort(__float2bfloat16(v1));
                        } else {
                            __nv_bfloat16 h0 = __float2bfloat16(v0);
                            __nv_bfloat16 h1 = __float2bfloat16(v1);
                            b0 = __bfloat16_as_ushort(__float2bfloat16(v0 - __bfloat162float(h0)));
                            b1 = __bfloat16_as_ushort(__float2bfloat16(v1 - __bfloat162float(h1)));
                        }
                        wr[k] = (uint32_t)b0 | ((uint32_t)b1 << 16);
                    }
                    wr0 = wr[0]; wr1 = wr[1]; wr2 = wr[2]; wr3 = wr[3];
                }
                uint32_t addr = swz(zb, feat, g8 * 16);
                asm volatile("st.shared.v4.b32 [%0], {%1,%2,%3,%4};"
                             :: "r"(addr), "r"(wr0), "r"(wr1), "r"(wr2), "r"(wr3));
            }
            __syncthreads();

            // ---- MMA over this 64-token tile: 4 x K16 steps ----
#pragma unroll
            for (int k16 = 0; k16 < 4; k16++) {
                const int kb = k16 * 32;
                uint32_t ah[4], al[4];
                // A frags (16x16): lanes 0-15 rows, lanes 16-31 k-high half
                ldsm4(ah, swz(zhb, r0w + (lane & 15), kb + (lane >> 4) * 16));
                ldsm4(al, swz(zlb, r0w + (lane & 15), kb + (lane >> 4) * 16));
#pragma unroll
                for (int nt2 = 0; nt2 < 4; nt2++) {
                    uint32_t bh[4], bl[4];
                    const int brow = nt2 * 16 + ((lane >> 4) & 1) * 8 + (lane & 7);
                    const int bkb  = kb + ((lane >> 3) & 1) * 16;
                    ldsm4(bh, swz(zhb, brow, bkb));
                    ldsm4(bl, swz(zlb, brow, bkb));
                    const int i0 = nt2 * 8;
                    mma16816(d00 + i0,     ah, bh);
                    mma16816(d00 + i0 + 4, ah, bh + 2);
                    mma16816(d01 + i0,     ah, bl);
                    mma16816(d01 + i0 + 4, ah, bl + 2);
                    mma16816(d11 + i0,     al, bl);
                    mma16816(d11 + i0 + 4, al, bl + 2);
                }
            }
            __syncthreads();      // before restaging z (and before comb reuse)
        }

        // ---- fold quadrants into comb (G = D00 + D01 + D01^T + D11) ----
        float* comb = sm.comb;
        {
#pragma unroll
            for (int nt = 0; nt < 8; nt++) {
                const int cb = nt * 8 + (lane & 3) * 2;
                const int r  = r0w + (lane >> 2);
                comb[r * 65 + cb]           = d00[nt*4+0] + d11[nt*4+0] + d01[nt*4+0];
                comb[r * 65 + cb + 1]       = d00[nt*4+1] + d11[nt*4+1] + d01[nt*4+1];
                comb[(r + 8) * 65 + cb]     = d00[nt*4+2] + d11[nt*4+2] + d01[nt*4+2];
                comb[(r + 8) * 65 + cb + 1] = d00[nt*4+3] + d11[nt*4+3] + d01[nt*4+3];
            }
        }
        __syncthreads();
        {
#pragma unroll
            for (int nt = 0; nt < 8; nt++) {
                const int cb = nt * 8 + (lane & 3) * 2;
                const int r  = r0w + (lane >> 2);
                comb[cb * 65 + r]           += d01[nt*4+0];
                comb[(cb + 1) * 65 + r]     += d01[nt*4+1];
                comb[cb * 65 + r + 8]       += d01[nt*4+2];
                comb[(cb + 1) * 65 + r + 8] += d01[nt*4+3];
            }
        }
        __syncthreads();

        float* dst = g_Gpart + (size_t)bid * (DD * DD);
        for (int e = tid; e < DD * DD; e += 128)
            dst[e] = comb[(e >> 6) * 65 + (e & 63)];
    }

    bar_arrive(0, NBLK);

    // ================= Blocks 128..255: phase B then exit ==================
    if (bid >= 128) {
        bar_wait(0);
        const int le = tid & 31;
        const int g  = tid >> 5;                   // 0..3
        const int e  = (bid - 128) * 32 + le;      // 0..4095
        const int i = e >> 6, j = e & 63;
        const int src = (i <= j) ? e : (j * 64 + i);

        float s = 0.0f;
        for (int p = g; p < NPART; p += 4)
            s += g_Gpart[(size_t)p * (DD * DD) + src];

        sm.red[tid] = s;
        __syncthreads();
        if (tid < 64) sm.red[tid] += sm.red[tid + 64];
        __syncthreads();
        if (tid < 32) g_G[e] = sm.red[tid] + sm.red[tid + 32];

        bar_arrive(1, 128);
        return;
    }

    // ================= Blocks 0..127: task math ============================
    {
        const int t  = bid;
        const int m  = (t >> 1) + 1;      // P = 2
        const int nt = 128;
        SmemC& S = sm.c;

        // ---- W-only pre-phase (overlaps phase B) ----
        if (tid < DD) { S.pm[tid] = perms[t * DD + tid]; S.Mf[tid] = 0.0f; }
        __syncthreads();
        if (tid >= m && tid < DD) S.Mf[S.pm[tid]] = 1.0f;
        __syncthreads();

        for (int idx = tid; idx < DD * KF; idx += nt) {
            int o = idx >> 4;
            S.Wm[idx] = W[idx] * S.Mf[o];
        }
        for (int idx = tid; idx < m * KF; idx += nt) {
            int j = idx >> 4, s = idx & 15;
            S.wjs[idx] = W[S.pm[j] * KF + s];
        }
        __syncthreads();

        for (int idx = tid; idx < KF * KF; idx += nt) {
            int s = idx >> 4, u = idx & 15;
            float acc = (s == u) ? 0.1f : 0.0f;
            for (int o = 0; o < DD; o++)
                acc += S.Wm[o * KF + s] * S.Wm[o * KF + u];
            S.C[idx] = acc;
        }
        __syncthreads();

        if (tid < 32) {      // warp 0: Gauss-Jordan inverse (SPD)
            const int la = tid;
            for (int k = 0; k < KF; k++) {
                if (la < KF) S.fcol[la] = S.C[la * KF + k];
                __syncwarp();
                float ip = 1.0f / S.fcol[k];
                if (la < KF)
                    S.C[k * KF + la] = (la == k) ? ip : S.C[k * KF + la] * ip;
                __syncwarp();
#pragma unroll
                for (int q = 0; q < 8; q++) {
                    int idx = la + 32 * q;
                    int i = idx >> 4, j = idx & 15;
                    if (i != k) {
                        float f = S.fcol[i];
                        S.C[idx] = (j == k) ? (-f * ip) : (S.C[idx] - f * S.C[k * KF + j]);
                    }
                }
                __syncwarp();
            }
        }
        __syncthreads();

        // ---- G-dependent post-phase ----
        bar_wait(1);

        for (int idx = tid; idx < 1024; idx += nt)
            ((float4*)S.Gsh)[idx] = ((const float4*)g_G)[idx];
        __syncthreads();

        for (int idx = tid; idx < DD * KF; idx += nt) {
            int d = idx >> 4, s = idx & 15;
            float acc = 0.0f;
            for (int o = 0; o < DD; o++)
                acc += S.Gsh[d * DD + o] * S.Wm[o * KF + s];
            S.Tfull[idx] = acc;
        }
        __syncthreads();

        for (int idx = tid; idx < KF * KF; idx += nt) {
            int s = idx >> 4, u = idx & 15;
            float acc = 0.0f;
            for (int o = 0; o < DD; o++)
                acc += S.Wm[o * KF + s] * S.Tfull[o * KF + u];
            S.H[idx] = acc;
        }
        __syncthreads();

        if (tid < m) {
            int j = tid;
            int pj = S.pm[j];
            float w[KF], b[KF];
#pragma unroll
            for (int s = 0; s < KF; s++) w[s] = S.wjs[j * KF + s];
#pragma unroll
            for (int s = 0; s < KF; s++) {
                float acc = 0.0f;
#pragma unroll
                for (int u2 = 0; u2 < KF; u2++) acc += S.C[s * KF + u2] * w[u2];
                b[s] = acc;
            }
            float wb = 0.0f, bu = 0.0f;
#pragma unroll
            for (int s = 0; s < KF; s++) {
                wb += w[s] * b[s];
                bu += b[s] * S.Tfull[pj * KF + s];
            }
            float v = 0.1f * (1.0f + wb);

            float bHb = 0.0f;
#pragma unroll
            for (int s = 0; s < KF; s++) {
                float acc = 0.0f;
#pragma unroll
                for (int u2 = 0; u2 < KF; u2++) acc += S.H[s * KF + u2] * b[u2];
                bHb += b[s] * acc;
            }
            float q = S.Gsh[pj * DD + pj] - 2.0f * bu + bHb;

            const float LOG2PI = 1.8378770664093453f;
            S.tbuf[j] = -0.5f * logf(v) - 0.5f * LOG2PI - 0.5f * q / (v * (float)n);
        }
        __syncthreads();

        if (tid == 0) {
            float s = 0.0f;
            for (int j = 0; j < m; j++) s += S.tbuf[j];
            g_task[t] = s / (float)(PP * m);
        }

        __threadfence();
        if (tid == 0) {
            int d = atomicAdd(&g_ctr, 1);
            S.isLast = (d == NTASK - 1);
        }
        __syncthreads();
        if (S.isLast) {
            S.fin[tid] = __ldcg(&g_task[tid]);    // 128 threads == NTASK
            __syncthreads();
            for (int ofs = NTASK / 2; ofs > 0; ofs >>= 1) {
                if (tid < ofs) S.fin[tid] += S.fin[tid + ofs];
                __syncthreads();
            }
            if (tid == 0) {
                out[0] = -S.fin[0];
                g_ctr = 0;
                g_go[0] = 0;
                g_go[1] = 0;
            }
        }
    }
}

// ---------------------------------------------------------------------------
extern "C" void kernel_launch(void* const* d_in, const int* in_sizes, int n_in,
                              void* d_out, int out_size) {
    const float* x = nullptr;
    const float* W = nullptr;
    const int* perms = nullptr;
    int nx = 0;
    for (int i = 0; i < n_in; i++) {
        if (in_sizes[i] == DD * KF)            W = (const float*)d_in[i];
        else if (in_sizes[i] == DD * PP * DD)  perms = (const int*)d_in[i];
        else { x = (const float*)d_in[i]; nx = in_sizes[i]; }
    }
    int n = nx / DD;
    int tpb = ((n + NBLK - 1) / NBLK + 63) & ~63;   // 256 for n=65536

    k_fused<<<NBLK, 128>>>(x, n, tpb, W, perms, (float*)d_out);
}

// round 16
// speedup vs baseline: 1.7135x; 1.0430x over previous
#include <cuda_runtime.h>
#include <cuda_bf16.h>
#include <stdint.h>
#include <math.h>

#define DD 64
#define KF 16
#define PP 2
#define NTASK 128
#define NBLK 256
#define NPART 256

__device__ __align__(16) float g_Gpart[NPART * DD * DD];
__device__ __align__(16) float g_G[DD * DD];
__device__ float g_task[NTASK];
__device__ int   g_ctr;
__device__ int   g_bar[2];
__device__ volatile int g_go[2];

// ---------------- warp-MMA helpers (baseline PTX, sm_80+) ----------------
__device__ __forceinline__ uint32_t smem_u32(const void* p) {
    uint32_t a;
    asm("{ .reg .u64 t; cvta.to.shared.u64 t, %1; cvt.u32.u64 %0, t; }"
        : "=r"(a) : "l"(p));
    return a;
}
__device__ __forceinline__ void ldsm4(uint32_t* r, uint32_t addr) {
    asm volatile("ldmatrix.sync.aligned.m8n8.x4.shared.b16 {%0,%1,%2,%3}, [%4];"
                 : "=r"(r[0]), "=r"(r[1]), "=r"(r[2]), "=r"(r[3]) : "r"(addr));
}
__device__ __forceinline__ void mma16816(float* c, const uint32_t* a,
                                         const uint32_t* b) {
    asm volatile(
        "mma.sync.aligned.m16n8k16.row.col.f32.bf16.bf16.f32 "
        "{%0,%1,%2,%3}, {%4,%5,%6,%7}, {%8,%9}, {%0,%1,%2,%3};"
        : "+f"(c[0]), "+f"(c[1]), "+f"(c[2]), "+f"(c[3])
        : "r"(a[0]), "r"(a[1]), "r"(a[2]), "r"(a[3]), "r"(b[0]), "r"(b[1]));
}
// swizzled smem byte address: 128B rows, SW128 (off ^ ((off>>3)&0x70))
__device__ __forceinline__ uint32_t swz(uint32_t base, int row, int kb) {
    uint32_t off = (uint32_t)row * 128u + (uint32_t)kb;
    return base + (off ^ ((off >> 3) & 0x70u));
}

// ---------------- shared layouts ----------------
struct SmemC {
    float Gsh[DD * DD];
    float Wm[DD * KF];
    float wjs[DD * KF];
    float Tfull[DD * KF];
    float C[KF * KF];
    float H[KF * KF];
    float fcol[KF];
    float Mf[DD];
    float tbuf[DD];
    float fin[NTASK];
    int   pm[DD];
    int   isLast;
};
struct SmemA {
    __align__(1024) __nv_bfloat16 zh[64 * 64];   // 8 KB, 128B rows
    __align__(1024) __nv_bfloat16 zl[64 * 64];   // 8 KB
};
union Smem {
    SmemA a;
    float comb[64 * 65];      // 16.6 KB (used after MMA; overlaps z)
    float red[256];
    SmemC c;
};

// grid barrier: arrive-only + volatile-load wait (replay-safe)
__device__ __forceinline__ void bar_arrive(int id, int total) {
    __syncthreads();
    if (threadIdx.x == 0) {
        __threadfence();
        int v = atomicAdd(&g_bar[id], 1);
        if (v == total - 1) {
            g_bar[id] = 0;
            __threadfence();
            g_go[id] = 1;
        }
    }
}
__device__ __forceinline__ void bar_wait(int id) {
    if (threadIdx.x == 0) {
        while (g_go[id] == 0) { __nanosleep(64); }
    }
    __syncthreads();
    __threadfence();
}

// ---------------------------------------------------------------------------
__global__ __launch_bounds__(256, 2)
void k_fused(const float* __restrict__ x, int n, int tpb,
             const float* __restrict__ W, const int* __restrict__ perms,
             float* __restrict__ out) {
    __shared__ Smem sm;
    const int tid = threadIdx.x;
    const int bid = blockIdx.x;
    const int wid = tid >> 5;
    const int lane = tid & 31;

    // ================= Phase A: split-bf16 SYRK on mma.sync ================
    // 8 warps: warp w -> rows (w&3)*16, col-half (w>>2)*32.
    {
        const int ntiles = tpb >> 6;
        const int feat = tid & 63;
        const int q    = tid >> 6;            // 0..3
        const bool isL = (q >= 2);
        const int toko = (q & 1) * 32;        // token sub-range
        const uint32_t zhb = smem_u32(sm.a.zh);
        const uint32_t zlb = smem_u32(sm.a.zl);
        const uint32_t zb  = isL ? zlb : zhb;
        const int r0w = (wid & 3) * 16;       // output rows
        const int ch  = wid >> 2;             // column half (0/1)

        float d00[16], d01[16], d11[16];
#pragma unroll
        for (int i = 0; i < 16; i++) { d00[i] = 0.f; d01[i] = 0.f; d11[i] = 0.f; }

        for (int t = 0; t < ntiles; t++) {
            // ---- stage h/l tiles: thread = (feat, quarter), 32 tokens ----
            const long tokg = (long)bid * tpb + (long)t * 64;
#pragma unroll
            for (int g8 = 0; g8 < 4; g8++) {
                uint32_t wr0, wr1, wr2, wr3;
                {
                    uint32_t wr[4];
#pragma unroll
                    for (int k = 0; k < 4; k++) {
                        long t0 = tokg + toko + g8 * 8 + 2 * k;
                        float v0 = (t0     < n) ? x[t0 * 64 + feat]       : 0.0f;
                        float v1 = (t0 + 1 < n) ? x[(t0 + 1) * 64 + feat] : 0.0f;
                        unsigned short b0, b1;
                        if (!isL) {
                            b0 = __bfloat16_as_ushort(__float2bfloat16(v0));
                            b1 = __bfloat16_as_ushort(__float2bfloat16(v1));
                        } else {
                            __nv_bfloat16 h0 = __float2bfloat16(v0);
                            __nv_bfloat16 h1 = __float2bfloat16(v1);
                            b0 = __bfloat16_as_ushort(__float2bfloat16(v0 - __bfloat162float(h0)));
                            b1 = __bfloat16_as_ushort(__float2bfloat16(v1 - __bfloat162float(h1)));
                        }
                        wr[k] = (uint32_t)b0 | ((uint32_t)b1 << 16);
                    }
                    wr0 = wr[0]; wr1 = wr[1]; wr2 = wr[2]; wr3 = wr[3];
                }
                uint32_t addr = swz(zb, feat, toko * 2 + g8 * 16);
                asm volatile("st.shared.v4.b32 [%0], {%1,%2,%3,%4};"
                             :: "r"(addr), "r"(wr0), "r"(wr1), "r"(wr2), "r"(wr3));
            }
            __syncthreads();

            // ---- MMA over this 64-token tile: 4 x K16 steps ----
#pragma unroll
            for (int k16 = 0; k16 < 4; k16++) {
                const int kb = k16 * 32;
                uint32_t ah[4], al[4];
                ldsm4(ah, swz(zhb, r0w + (lane & 15), kb + (lane >> 4) * 16));
                ldsm4(al, swz(zlb, r0w + (lane & 15), kb + (lane >> 4) * 16));
#pragma unroll
                for (int nt2 = 0; nt2 < 2; nt2++) {
                    uint32_t bh[4], bl[4];
                    const int ntg  = ch * 2 + nt2;     // global 16-col tile
                    const int brow = ntg * 16 + ((lane >> 4) & 1) * 8 + (lane & 7);
                    const int bkb  = kb + ((lane >> 3) & 1) * 16;
                    ldsm4(bh, swz(zhb, brow, bkb));
                    ldsm4(bl, swz(zlb, brow, bkb));
                    const int i0 = nt2 * 8;
                    mma16816(d00 + i0,     ah, bh);
                    mma16816(d00 + i0 + 4, ah, bh + 2);
                    mma16816(d01 + i0,     ah, bl);
                    mma16816(d01 + i0 + 4, ah, bl + 2);
                    mma16816(d11 + i0,     al, bl);
                    mma16816(d11 + i0 + 4, al, bl + 2);
                }
            }
            __syncthreads();      // before restaging z (and before comb reuse)
        }

        // ---- fold quadrants into comb (G = D00 + D01 + D01^T + D11) ----
        float* comb = sm.comb;
        {
#pragma unroll
            for (int ntl = 0; ntl < 4; ntl++) {
                const int base = (ntl >> 1) * 8 + (ntl & 1) * 4;
                const int cb = ch * 32 + ntl * 8 + (lane & 3) * 2;
                const int r  = r0w + (lane >> 2);
                comb[r * 65 + cb]           = d00[base+0] + d11[base+0] + d01[base+0];
                comb[r * 65 + cb + 1]       = d00[base+1] + d11[base+1] + d01[base+1];
                comb[(r + 8) * 65 + cb]     = d00[base+2] + d11[base+2] + d01[base+2];
                comb[(r + 8) * 65 + cb + 1] = d00[base+3] + d11[base+3] + d01[base+3];
            }
        }
        __syncthreads();
        {
#pragma unroll
            for (int ntl = 0; ntl < 4; ntl++) {
                const int base = (ntl >> 1) * 8 + (ntl & 1) * 4;
                const int cb = ch * 32 + ntl * 8 + (lane & 3) * 2;
                const int r  = r0w + (lane >> 2);
                comb[cb * 65 + r]           += d01[base+0];
                comb[(cb + 1) * 65 + r]     += d01[base+1];
                comb[cb * 65 + r + 8]       += d01[base+2];
                comb[(cb + 1) * 65 + r + 8] += d01[base+3];
            }
        }
        __syncthreads();

        float* dst = g_Gpart + (size_t)bid * (DD * DD);
        for (int e = tid; e < DD * DD; e += 256)
            dst[e] = comb[(e >> 6) * 65 + (e & 63)];
    }

    bar_arrive(0, NBLK);

    // ================= Blocks 128..255: phase B then exit ==================
    if (bid >= 128) {
        bar_wait(0);
        const int le = tid & 31;
        const int g  = tid >> 5;                   // 0..7
        const int e  = (bid - 128) * 32 + le;      // 0..4095
        const int i = e >> 6, j = e & 63;
        const int src = (i <= j) ? e : (j * 64 + i);

        float s = 0.0f;
        for (int p = g; p < NPART; p += 8)
            s += g_Gpart[(size_t)p * (DD * DD) + src];

        sm.red[tid] = s;
        __syncthreads();
        if (tid < 128) sm.red[tid] += sm.red[tid + 128];
        __syncthreads();
        if (tid < 64) sm.red[tid] += sm.red[tid + 64];
        __syncthreads();
        if (tid < 32) g_G[e] = sm.red[tid] + sm.red[tid + 32];

        bar_arrive(1, 128);
        return;
    }

    // ================= Blocks 0..127: task math ============================
    {
        const int t  = bid;
        const int m  = (t >> 1) + 1;      // P = 2
        const int nt = 256;
        SmemC& S = sm.c;

        // ---- W-only pre-phase (overlaps phase B) ----
        if (tid < DD) { S.pm[tid] = perms[t * DD + tid]; S.Mf[tid] = 0.0f; }
        __syncthreads();
        if (tid >= m && tid < DD) S.Mf[S.pm[tid]] = 1.0f;
        __syncthreads();

        for (int idx = tid; idx < DD * KF; idx += nt) {
            int o = idx >> 4;
            S.Wm[idx] = W[idx] * S.Mf[o];
        }
        for (int idx = tid; idx < m * KF; idx += nt) {
            int j = idx >> 4, s = idx & 15;
            S.wjs[idx] = W[S.pm[j] * KF + s];
        }
        __syncthreads();

        for (int idx = tid; idx < KF * KF; idx += nt) {
            int s = idx >> 4, u = idx & 15;
            float acc = (s == u) ? 0.1f : 0.0f;
            for (int o = 0; o < DD; o++)
                acc += S.Wm[o * KF + s] * S.Wm[o * KF + u];
            S.C[idx] = acc;
        }
        __syncthreads();

        if (tid < 32) {      // warp 0: Gauss-Jordan inverse (SPD)
            const int la = tid;
            for (int k = 0; k < KF; k++) {
                if (la < KF) S.fcol[la] = S.C[la * KF + k];
                __syncwarp();
                float ip = 1.0f / S.fcol[k];
                if (la < KF)
                    S.C[k * KF + la] = (la == k) ? ip : S.C[k * KF + la] * ip;
                __syncwarp();
#pragma unroll
                for (int qq = 0; qq < 8; qq++) {
                    int idx = la + 32 * qq;
                    int i = idx >> 4, j = idx & 15;
                    if (i != k) {
                        float f = S.fcol[i];
                        S.C[idx] = (j == k) ? (-f * ip) : (S.C[idx] - f * S.C[k * KF + j]);
                    }
                }
                __syncwarp();
            }
        }
        __syncthreads();

        // ---- G-dependent post-phase ----
        bar_wait(1);

        for (int idx = tid; idx < 1024; idx += nt)
            ((float4*)S.Gsh)[idx] = ((const float4*)g_G)[idx];
        __syncthreads();

        for (int idx = tid; idx < DD * KF; idx += nt) {
            int d = idx >> 4, s = idx & 15;
            float acc = 0.0f;
            for (int o = 0; o < DD; o++)
                acc += S.Gsh[d * DD + o] * S.Wm[o * KF + s];
            S.Tfull[idx] = acc;
        }
        __syncthreads();

        for (int idx = tid; idx < KF * KF; idx += nt) {
            int s = idx >> 4, u = idx & 15;
            float acc = 0.0f;
            for (int o = 0; o < DD; o++)
                acc += S.Wm[o * KF + s] * S.Tfull[o * KF + u];
            S.H[idx] = acc;
        }
        __syncthreads();

        if (tid < m) {
            int j = tid;
            int pj = S.pm[j];
            float w[KF], b[KF];
#pragma unroll
            for (int s = 0; s < KF; s++) w[s] = S.wjs[j * KF + s];
#pragma unroll
            for (int s = 0; s < KF; s++) {
                float acc = 0.0f;
#pragma unroll
                for (int u2 = 0; u2 < KF; u2++) acc += S.C[s * KF + u2] * w[u2];
                b[s] = acc;
            }
            float wb = 0.0f, bu = 0.0f;
#pragma unroll
            for (int s = 0; s < KF; s++) {
                wb += w[s] * b[s];
                bu += b[s] * S.Tfull[pj * KF + s];
            }
            float v = 0.1f * (1.0f + wb);

            float bHb = 0.0f;
#pragma unroll
            for (int s = 0; s < KF; s++) {
                float acc = 0.0f;
#pragma unroll
                for (int u2 = 0; u2 < KF; u2++) acc += S.H[s * KF + u2] * b[u2];
                bHb += b[s] * acc;
            }
            float q = S.Gsh[pj * DD + pj] - 2.0f * bu + bHb;

            const float LOG2PI = 1.8378770664093453f;
            S.tbuf[j] = -0.5f * logf(v) - 0.5f * LOG2PI - 0.5f * q / (v * (float)n);
        }
        __syncthreads();

        if (tid == 0) {
            float s = 0.0f;
            for (int j = 0; j < m; j++) s += S.tbuf[j];
            g_task[t] = s / (float)(PP * m);
        }

        __threadfence();
        if (tid == 0) {
            int d = atomicAdd(&g_ctr, 1);
            S.isLast = (d == NTASK - 1);
        }
        __syncthreads();
        if (S.isLast) {
            if (tid < NTASK) S.fin[tid] = __ldcg(&g_task[tid]);
            __syncthreads();
            for (int ofs = NTASK / 2; ofs > 0; ofs >>= 1) {
                if (tid < ofs) S.fin[tid] += S.fin[tid + ofs];
                __syncthreads();
            }
            if (tid == 0) {
                out[0] = -S.fin[0];
                g_ctr = 0;
                g_go[0] = 0;
                g_go[1] = 0;
            }
        }
    }
}

// ---------------------------------------------------------------------------
extern "C" void kernel_launch(void* const* d_in, const int* in_sizes, int n_in,
                              void* d_out, int out_size) {
    const float* x = nullptr;
    const float* W = nullptr;
    const int* perms = nullptr;
    int nx = 0;
    for (int i = 0; i < n_in; i++) {
        if (in_sizes[i] == DD * KF)            W = (const float*)d_in[i];
        else if (in_sizes[i] == DD * PP * DD)  perms = (const int*)d_in[i];
        else { x = (const float*)d_in[i]; nx = in_sizes[i]; }
    }
    int n = nx / DD;
    int tpb = ((n + NBLK - 1) / NBLK + 63) & ~63;   // 256 for n=65536

    k_fused<<<NBLK, 256>>>(x, n, tpb, W, perms, (float*)d_out);
}